// round 1
// baseline (speedup 1.0000x reference)
#include <cuda_runtime.h>
#include <cuda_bf16.h>

#define B_  4
#define S_  1024
#define D_  2048
#define H_  16
#define HD_ 128

// Scratch (allocation-free rule): head-major [b,h,s,d] fp32 q/k/v
__device__ float g_q[B_*H_*S_*HD_];
__device__ float g_k[B_*H_*S_*HD_];
__device__ float g_v[B_*H_*S_*HD_];

// ---------------------------------------------------------------------------
// Kernel 1: QKV GEMM.  out[m,n] = sum_k A[m,k]*W[n,k] + bias[n]
// M=4096 (b*s), N=6144 (e), K=2048.  BM=BN=128, BK=8, 256 thr, 8x8 microtile.
// Epilogue scatters into g_q/g_k/g_v in [b,h,s,d] layout.
// ---------------------------------------------------------------------------
__global__ __launch_bounds__(256) void qkv_gemm(const float* __restrict__ A,
                                                const float* __restrict__ W,
                                                const float* __restrict__ bias) {
    __shared__ float As[8][128];
    __shared__ float Bs[8][128];
    int tid = threadIdx.x;
    int bm = blockIdx.y * 128, bn = blockIdx.x * 128;
    int lr = tid >> 1;          // 0..127: row within tile
    int lk = (tid & 1) * 4;     // 0 or 4: k offset
    const float* Ap = A + (size_t)(bm + lr) * D_ + lk;
    const float* Wp = W + (size_t)(bn + lr) * D_ + lk;
    int tx = tid & 15, ty = tid >> 4;

    float acc[8][8];
#pragma unroll
    for (int i = 0; i < 8; i++)
#pragma unroll
        for (int j = 0; j < 8; j++) acc[i][j] = 0.f;

    for (int k0 = 0; k0 < D_; k0 += 8) {
        float4 a4 = *(const float4*)(Ap + k0);
        float4 b4 = *(const float4*)(Wp + k0);
        __syncthreads();   // previous iteration's reads complete
        As[lk+0][lr] = a4.x; As[lk+1][lr] = a4.y; As[lk+2][lr] = a4.z; As[lk+3][lr] = a4.w;
        Bs[lk+0][lr] = b4.x; Bs[lk+1][lr] = b4.y; Bs[lk+2][lr] = b4.z; Bs[lk+3][lr] = b4.w;
        __syncthreads();
#pragma unroll
        for (int kk = 0; kk < 8; kk++) {
            float4 a0 = *(const float4*)&As[kk][ty*4];
            float4 a1 = *(const float4*)&As[kk][ty*4 + 64];
            float4 b0 = *(const float4*)&Bs[kk][tx*4];
            float4 b1 = *(const float4*)&Bs[kk][tx*4 + 64];
            float ra[8] = {a0.x,a0.y,a0.z,a0.w,a1.x,a1.y,a1.z,a1.w};
            float rb[8] = {b0.x,b0.y,b0.z,b0.w,b1.x,b1.y,b1.z,b1.w};
#pragma unroll
            for (int i = 0; i < 8; i++)
#pragma unroll
                for (int j = 0; j < 8; j++)
                    acc[i][j] += ra[i] * rb[j];
        }
    }

#pragma unroll
    for (int i = 0; i < 8; i++) {
        int m = bm + ((i < 4) ? ty*4 + i : 64 + ty*4 + (i - 4));
        int b = m >> 10, s = m & 1023;
#pragma unroll
        for (int j = 0; j < 8; j++) {
            int n = bn + ((j < 4) ? tx*4 + j : 64 + tx*4 + (j - 4));
            float v = acc[i][j] + bias[n];
            int h = n / 384;
            int inner = n - h * 384;
            int part = inner >> 7;      // 0=q, 1=k, 2=v
            int dd = inner & 127;
            float* dst = (part == 0) ? g_q : (part == 1) ? g_k : g_v;
            dst[((size_t)((b*H_ + h)*S_ + s)) * HD_ + dd] = v;
        }
    }
}

// ---------------------------------------------------------------------------
// Kernel 2: RoPE in-place on q or k.  Pair (j, j+64) per thread.
// ---------------------------------------------------------------------------
__global__ __launch_bounds__(256) void rope_kernel(int which) {
    float* x = which ? g_k : g_q;
    int i = blockIdx.x * blockDim.x + threadIdx.x;
    const int total = B_ * H_ * S_ * 64;
    if (i >= total) return;
    int j = i & 63;
    int bhs = i >> 6;
    int s = bhs & (S_ - 1);
    // inv_freq[j] = 10000^(-j/64) = 2^(-j*log2(10000)/64)
    float ang = (float)s * exp2f(-(float)j * (13.287712379549449f / 64.f));
    float sn, c;
    sincosf(ang, &sn, &c);
    float* p = x + (size_t)bhs * HD_ + j;
    float x1 = p[0], x2 = p[64];
    p[0]  = x1 * c - x2 * sn;
    p[64] = x2 * c + x1 * sn;
}

// ---------------------------------------------------------------------------
// Kernel 3: causal flash attention, fp32.
// One CTA = (b,h) pair x 64-row q tile.  256 threads.
// Smem: Qs[64][129], Ks[64][129] (pad-129: conflict-free scalar GEMM reads),
//       Vs[64][128], Sc[64][65] (pad-65: conflict-free P reads), row state.
// ---------------------------------------------------------------------------
#define ATTN_SMEM_FLOATS (64*129*2 + 64*128 + 64*65 + 64*3)
#define ATTN_SMEM_BYTES  (ATTN_SMEM_FLOATS * 4)

__global__ __launch_bounds__(256) void attn_kernel(float* __restrict__ out) {
    extern __shared__ float sm[];
    float* Qs   = sm;                 // [64][129]
    float* Ks   = Qs + 64*129;        // [64][129]
    float* Vs   = Ks + 64*129;        // [64][128]
    float* Sc   = Vs + 64*128;        // [64][65]
    float* rowm = Sc + 64*65;
    float* rowl = rowm + 64;
    float* corr = rowl + 64;

    int tid = threadIdx.x;
    int qt = blockIdx.x, bh = blockIdx.y;
    int q0 = qt * 64;
    const float* Qb = g_q + (size_t)bh * S_ * HD_;
    const float* Kb = g_k + (size_t)bh * S_ * HD_;
    const float* Vb = g_v + (size_t)bh * S_ * HD_;

    const float scale = 0.08838834764831845f;  // 1/sqrt(128)
    {
        int c = tid & 127, r0 = tid >> 7;
#pragma unroll
        for (int it = 0; it < 32; it++) {
            int r = r0 + it * 2;
            Qs[r*129 + c] = Qb[(size_t)(q0 + r)*HD_ + c] * scale;
        }
    }
    if (tid < 64) { rowm[tid] = -1e30f; rowl[tid] = 0.f; }

    float o[32];
#pragma unroll
    for (int i = 0; i < 32; i++) o[i] = 0.f;

    int m = tid & 63, g = tid >> 6;       // PV layout: row m, 32-col group g
    int tx = tid & 15, ty = tid >> 4;     // QK layout: 16x16 grid, 4x4 microtile

    for (int kt = 0; kt <= qt; kt++) {
        int k0 = kt * 64;
        __syncthreads();  // previous iteration's smem reads complete
        {
            int c = tid & 127, r0 = tid >> 7;
#pragma unroll
            for (int it = 0; it < 32; it++) {
                int r = r0 + it * 2;
                Ks[r*129 + c] = Kb[(size_t)(k0 + r)*HD_ + c];
                Vs[r*128 + c] = Vb[(size_t)(k0 + r)*HD_ + c];
            }
        }
        __syncthreads();

        // ---- S = Q K^T  (4x4 per thread) ----
        float acc[4][4];
#pragma unroll
        for (int i = 0; i < 4; i++)
#pragma unroll
            for (int j = 0; j < 4; j++) acc[i][j] = 0.f;

#pragma unroll 4
        for (int kk = 0; kk < 128; kk++) {
            float a_[4], b_[4];
#pragma unroll
            for (int i = 0; i < 4; i++) a_[i] = Qs[(ty*4 + i)*129 + kk];
#pragma unroll
            for (int j = 0; j < 4; j++) b_[j] = Ks[(tx*4 + j)*129 + kk];
#pragma unroll
            for (int i = 0; i < 4; i++)
#pragma unroll
                for (int j = 0; j < 4; j++)
                    acc[i][j] += a_[i] * b_[j];
        }

        bool diag = (kt == qt);
#pragma unroll
        for (int i = 0; i < 4; i++) {
            int r = ty*4 + i;
#pragma unroll
            for (int j = 0; j < 4; j++) {
                int c = tx*4 + j;
                float v = acc[i][j];
                if (diag && c > r) v = -1e30f;   // k0==q0 on diagonal tile
                Sc[r*65 + c] = v;
            }
        }
        __syncthreads();

        // ---- online softmax row pass (64 threads, 1 row each) ----
        if (tid < 64) {
            int r = tid;
            float mo = rowm[r], mx = mo;
#pragma unroll 8
            for (int c = 0; c < 64; c++) mx = fmaxf(mx, Sc[r*65 + c]);
            float co = __expf(mo - mx);
            float su = 0.f;
#pragma unroll 8
            for (int c = 0; c < 64; c++) {
                float p = __expf(Sc[r*65 + c] - mx);
                Sc[r*65 + c] = p;
                su += p;
            }
            rowl[r] = rowl[r] * co + su;
            rowm[r] = mx;
            corr[r] = co;
        }
        __syncthreads();

        // ---- O = O*corr + P V ----
        float co = corr[m];
#pragma unroll
        for (int i = 0; i < 32; i++) o[i] *= co;
#pragma unroll 4
        for (int n = 0; n < 64; n++) {
            float p = Sc[m*65 + n];
            const float4* vr = (const float4*)(Vs + n*128 + g*32);
#pragma unroll
            for (int i = 0; i < 8; i++) {
                float4 v4 = vr[i];
                o[i*4 + 0] += p * v4.x;
                o[i*4 + 1] += p * v4.y;
                o[i*4 + 2] += p * v4.z;
                o[i*4 + 3] += p * v4.w;
            }
        }
    }

    float invl = 1.f / rowl[m];
    int b = bh >> 4, h = bh & 15;
    int s = q0 + m;
    float* op = out + ((size_t)(b*S_ + s)) * D_ + h*HD_ + g*32;
#pragma unroll
    for (int i = 0; i < 32; i++) op[i] = o[i] * invl;
}

// ---------------------------------------------------------------------------
extern "C" void kernel_launch(void* const* d_in, const int* in_sizes, int n_in,
                              void* d_out, int out_size) {
    const float* hidden = (const float*)d_in[0];
    const float* w_qkv  = (const float*)d_in[1];
    const float* b_qkv  = (const float*)d_in[2];
    float* out = (float*)d_out;

    // 116 KB dynamic smem for attention (idempotent; legal during capture —
    // not a stream op, not an allocation)
    cudaFuncSetAttribute(attn_kernel, cudaFuncAttributeMaxDynamicSharedMemorySize,
                         ATTN_SMEM_BYTES);

    dim3 g1(6144 / 128, 4096 / 128);   // (48, 32)
    qkv_gemm<<<g1, 256>>>(hidden, w_qkv, b_qkv);

    int total = B_ * H_ * S_ * 64;
    int nb = (total + 255) / 256;
    rope_kernel<<<nb, 256>>>(0);
    rope_kernel<<<nb, 256>>>(1);

    attn_kernel<<<dim3(S_ / 64, B_ * H_), 256, ATTN_SMEM_BYTES>>>(out);
}